// round 8
// baseline (speedup 1.0000x reference)
#include <cuda_runtime.h>
#include <cstdint>
#include <cfloat>

// ---------------- problem constants ----------------
#define MROWS   65536
#define DDIM    64
#define KCODES  8192
#define TM      128                    // rows per CTA
#define TN      64                     // codes per tile
#define NTILES  128
#define NBLOCKS 512
#define NTHREADS 512
#define Q_ELEMS (MROWS * DDIM)
#define LOSS_OFF Q_ELEMS               // layout: [quantised | loss | indices]
#define IDX_OFF  (Q_ELEMS + 1)
#define FULL_OUT (Q_ELEMS + 1 + MROWS)

// Split-codebook tile layout: per (tile, split): 64 codes x 72 floats (padded)
// float2 at [n*72 + kk*8 + tig*2] = (e[d=kk*8+tig], e[d=kk*8+tig+4])
#define ES_N_STRIDE     72
#define ES_SPLIT_FLOATS (64 * ES_N_STRIDE)      // 4608
#define ES_TILE_FLOATS  (2 * ES_SPLIT_FLOATS)   // 9216
#define ES_TILE_BYTES   (ES_TILE_FLOATS * 4)    // 36864
#define ES_CHUNKS       (ES_TILE_FLOATS / 4)    // 2304 x 16B

#define ZS_STRIDE 68
#define ZS_FLOATS (TM * ZS_STRIDE)              // 8704
#define SMEM_TOTAL ((ZS_FLOATS + 2 * ES_TILE_FLOATS) * 4)   // 108544

__device__ float  g_zsq[MROWS];
__device__ double g_partial[NBLOCKS];
__device__ float  g_esplit[NTILES * ES_TILE_FLOATS];   // 4.7 MB

// ---------------- helpers ----------------
__device__ __forceinline__ float tf32rn(float x) {   // RN to tf32 grid
    uint32_t b = __float_as_uint(x);
    uint32_t r = b + 0x00000FFFu + ((b >> 13) & 1u);
    return __uint_as_float(r & 0xFFFFE000u);
}
__device__ __forceinline__ uint32_t smem_u32(const void* p) {
    uint32_t a;
    asm("{ .reg .u64 t; cvta.to.shared.u64 t, %1; cvt.u32.u64 %0, t; }" : "=r"(a) : "l"(p));
    return a;
}
__device__ __forceinline__ void cp16(uint32_t dst, const float* src) {
    asm volatile("cp.async.cg.shared.global [%0], [%1], 16;" :: "r"(dst), "l"(src));
}
#define CP_COMMIT() asm volatile("cp.async.commit_group;" ::: "memory")

// m16n8k8 tf32 mma: D += A*B
__device__ __forceinline__ void mma8(float* d, const uint32_t* a, uint32_t b0, uint32_t b1) {
    asm volatile("mma.sync.aligned.m16n8k8.row.col.f32.tf32.tf32.f32 "
                 "{%0,%1,%2,%3}, {%4,%5,%6,%7}, {%8,%9}, {%0,%1,%2,%3};"
                 : "+f"(d[0]), "+f"(d[1]), "+f"(d[2]), "+f"(d[3])
                 : "r"(a[0]), "r"(a[1]), "r"(a[2]), "r"(a[3]), "r"(b0), "r"(b1));
}

// ---------------- kernel 0: z row norms (fp64 -> fp32) ----------------
__global__ void zsq_kernel(const float* __restrict__ z) {
    int r = blockIdx.x * blockDim.x + threadIdx.x;
    if (r >= MROWS) return;
    const float4* p = (const float4*)(z + (size_t)r * DDIM);
    double s = 0.0;
#pragma unroll
    for (int i = 0; i < DDIM / 4; i++) {
        float4 v = p[i];
        s += (double)v.x * v.x + (double)v.y * v.y + (double)v.z * v.z + (double)v.w * v.w;
    }
    g_zsq[r] = (float)s;
}

// ---------------- kernel 1: tf32 2-way split of codebook ----------------
__global__ void split_cb(const float* __restrict__ cb) {
    int idx = blockIdx.x * blockDim.x + threadIdx.x;     // 8192 codes x 8 kk
    if (idx >= KCODES * 8) return;
    int k = idx >> 3, kk = idx & 7;
    int t = k >> 6, n = k & 63;
    const float4* p = (const float4*)(cb + (size_t)k * DDIM + kk * 8);
    float4 x = p[0], y = p[1];
    float e[8] = {x.x, x.y, x.z, x.w, y.x, y.y, y.z, y.w};
    float* base = g_esplit + (size_t)t * ES_TILE_FLOATS;
    int off = n * ES_N_STRIDE + kk * 8;
#pragma unroll
    for (int tig = 0; tig < 4; tig++) {
        float a = e[tig], b = e[tig + 4];
        float a1 = tf32rn(a), b1 = tf32rn(b);
        *(float2*)(base + off + tig * 2) = make_float2(a1, b1);
        *(float2*)(base + ES_SPLIT_FLOATS + off + tig * 2) = make_float2(a - a1, b - b1);
    }
}

// ---------------- kernel 2: tf32 mma GEMM + quantized argmin ----------------
__global__ void __launch_bounds__(NTHREADS) vq_main(const float* __restrict__ z,
                                                    const float* __restrict__ cb,
                                                    float* __restrict__ out,
                                                    int out_size) {
    extern __shared__ float smem[];
    float* Zs  = smem;                        // [128][68]: raw z, then z2 residuals
    float* Es0 = smem + ZS_FLOATS;
    float* Es1 = Es0 + ES_TILE_FLOATS;

    const int tid  = threadIdx.x;
    const int lane = tid & 31, wid = tid >> 5;
    const int g    = lane >> 2, tig = lane & 3;
    const int wg   = wid >> 1,  cg  = wid & 1;   // 8 row-groups x 2 code-groups
    const int rowBase = blockIdx.x * TM;
    const int rbase   = wg * 16;
    const int row0s   = (rbase + g) * ZS_STRIDE;        // smem row offsets
    const int row1s   = (rbase + g + 8) * ZS_STRIDE;

    const bool can_q   = (out_size >= Q_ELEMS);
    const bool can_idx = (out_size >= FULL_OUT);

    const uint32_t es0_u = smem_u32(Es0);
    const uint32_t es1_u = smem_u32(Es1);

    // ---- issue tile-0 codebook copy ----
    {
        const float* src = g_esplit;
#pragma unroll
        for (int i = 0; i < 5; i++) {
            int c = tid + i * NTHREADS;
            if (c < ES_CHUNKS) cp16(es0_u + c * 16, src + c * 4);
        }
        CP_COMMIT();
    }

    // ---- stage raw z tile into Zs ----
#pragma unroll
    for (int i = 0; i < 4; i++) {
        int v = tid + i * NTHREADS;
        int r = v >> 4, c4 = v & 15;
        float4 t4 = ((const float4*)(z + (size_t)(rowBase + r) * DDIM))[c4];
        *(float4*)&Zs[r * ZS_STRIDE + c4 * 4] = t4;
    }
    __syncthreads();

    // ---- build z1 fragments in registers (both cg warps, same rows) ----
    uint32_t z1f[8][4];
#pragma unroll
    for (int kk = 0; kk < 8; kk++) {
        int col = kk * 8 + tig;
        float v0 = Zs[row0s + col];
        float v1 = Zs[row1s + col];
        float v2 = Zs[row0s + col + 4];
        float v3 = Zs[row1s + col + 4];
        z1f[kk][0] = __float_as_uint(tf32rn(v0));
        z1f[kk][1] = __float_as_uint(tf32rn(v1));
        z1f[kk][2] = __float_as_uint(tf32rn(v2));
        z1f[kk][3] = __float_as_uint(tf32rn(v3));
    }
    __syncthreads();
    // cg==0 warps overwrite Zs with z2 = z - z1 (each position exactly once)
    if (cg == 0) {
#pragma unroll
        for (int kk = 0; kk < 8; kk++) {
            int col = kk * 8 + tig;
            Zs[row0s + col]     -= __uint_as_float(z1f[kk][0]);
            Zs[row1s + col]     -= __uint_as_float(z1f[kk][1]);
            Zs[row0s + col + 4] -= __uint_as_float(z1f[kk][2]);
            Zs[row1s + col + 4] -= __uint_as_float(z1f[kk][3]);
        }
    }

    float zsq0 = g_zsq[rowBase + rbase + g];
    float zsq1 = g_zsq[rowBase + rbase + g + 8];

    float best[2] = {FLT_MAX, FLT_MAX};
    int   bidx[2] = {0, 0};
    __syncthreads();

    // ---------------- mainloop over 128 code tiles ----------------
    for (int t = 0; t < NTILES; t++) {
        if (t + 1 < NTILES) {
            const float* src = g_esplit + (size_t)(t + 1) * ES_TILE_FLOATS;
            uint32_t du = ((t + 1) & 1) ? es1_u : es0_u;
#pragma unroll
            for (int i = 0; i < 5; i++) {
                int c = tid + i * NTHREADS;
                if (c < ES_CHUNKS) cp16(du + c * 16, src + c * 4);
            }
            CP_COMMIT();
            asm volatile("cp.async.wait_group 1;" ::: "memory");
        } else {
            asm volatile("cp.async.wait_group 0;" ::: "memory");
        }
        __syncthreads();

        const float* E1 = (t & 1) ? Es1 : Es0;
        const float* E2 = E1 + ES_SPLIT_FLOATS;

        float acc[4][4];
#pragma unroll
        for (int na = 0; na < 4; na++)
#pragma unroll
            for (int c = 0; c < 4; c++) acc[na][c] = 0.0f;

#pragma unroll
        for (int kk = 0; kk < 8; kk++) {
            int col = kk * 8 + tig;
            uint32_t z2f[4];
            z2f[0] = __float_as_uint(Zs[row0s + col]);
            z2f[1] = __float_as_uint(Zs[row1s + col]);
            z2f[2] = __float_as_uint(Zs[row0s + col + 4]);
            z2f[3] = __float_as_uint(Zs[row1s + col + 4]);
#pragma unroll
            for (int na = 0; na < 4; na++) {
                int n = cg * 32 + na * 8 + g;
                int foff = n * ES_N_STRIDE + kk * 8 + tig * 2;
                float2 b1v = *(const float2*)(E1 + foff);
                float2 b2v = *(const float2*)(E2 + foff);
                uint32_t b1x = __float_as_uint(b1v.x), b1y = __float_as_uint(b1v.y);
                uint32_t b2x = __float_as_uint(b2v.x), b2y = __float_as_uint(b2v.y);
                mma8(acc[na], z1f[kk], b2x, b2y);   // z1*e2 (small first)
                mma8(acc[na], z2f,     b1x, b1y);   // z2*e1
                mma8(acc[na], z1f[kk], b1x, b1y);   // z1*e1 (dominant last)
            }
        }

        // quantized scores: s = RN(z_sq - 2*dot); running argmin, ascending idx
#pragma unroll
        for (int na = 0; na < 4; na++) {
            int code0 = t * TN + cg * 32 + na * 8 + 2 * tig;
            float s0 = fmaf(-2.0f, acc[na][0], zsq0);
            float s1 = fmaf(-2.0f, acc[na][1], zsq0);
            float s2 = fmaf(-2.0f, acc[na][2], zsq1);
            float s3 = fmaf(-2.0f, acc[na][3], zsq1);
            if (s0 < best[0]) { best[0] = s0; bidx[0] = code0; }
            if (s1 < best[0]) { best[0] = s1; bidx[0] = code0 + 1; }
            if (s2 < best[1]) { best[1] = s2; bidx[1] = code0; }
            if (s3 < best[1]) { best[1] = s3; bidx[1] = code0 + 1; }
        }
        __syncthreads();
    }

    // ---- reduce across tig lanes (same rows), lowest-index tie-break ----
#pragma unroll
    for (int h = 0; h < 2; h++) {
        float bv = best[h];
        int   bi = bidx[h];
#pragma unroll
        for (int off = 1; off <= 2; off <<= 1) {
            float ov = __shfl_xor_sync(0xFFFFFFFFu, bv, off);
            int   oi = __shfl_xor_sync(0xFFFFFFFFu, bi, off);
            if (ov < bv || (ov == bv && oi < bi)) { bv = ov; bi = oi; }
        }
        best[h] = bv; bidx[h] = bi;
    }

    float2* red = (float2*)Zs;    // [128][2] candidates from the 2 code-groups
    if (tig == 0) {
#pragma unroll
        for (int h = 0; h < 2; h++)
            red[(rbase + g + h * 8) * 2 + cg] =
                make_float2(best[h], __int_as_float(bidx[h]));
    }
    __syncthreads();

    // ---- final per-row pick + outputs (exact quantised_st) + fp64 loss ----
    double lsum = 0.0;
    if (tid < TM) {
        int row = rowBase + tid;
        float2 c0 = red[tid * 2 + 0];
        float2 c1 = red[tid * 2 + 1];
        float bv = c0.x; int bi = __float_as_int(c0.y);
        int i1 = __float_as_int(c1.y);
        if (c1.x < bv || (c1.x == bv && i1 < bi)) { bv = c1.x; bi = i1; }
        if (can_idx) out[IDX_OFF + row] = (float)bi;
        const float4* q4 = (const float4*)(cb + (size_t)bi * DDIM);
        const float4* z4 = (const float4*)(z + (size_t)row * DDIM);
        float4* o4 = (float4*)(out + (size_t)row * DDIM);
#pragma unroll
        for (int i = 0; i < DDIM / 4; i++) {
            float4 q = q4[i];
            float4 zz = z4[i];
            // reference: quantised_st = z + (q - z), fp32 elementwise
            float dx = q.x - zz.x, dy = q.y - zz.y, dz = q.z - zz.z, dw = q.w - zz.w;
            if (can_q) {
                float4 o;
                o.x = zz.x + dx; o.y = zz.y + dy; o.z = zz.z + dz; o.w = zz.w + dw;
                o4[i] = o;
            }
            lsum += (double)(dx * dx) + (double)(dy * dy)
                  + (double)(dz * dz) + (double)(dw * dw);
        }
    }
    double* dred = (double*)(Zs + 1024);     // byte 4096.., clear of red[0..511]
    __syncthreads();
    dred[tid] = lsum;
    __syncthreads();
#pragma unroll
    for (int s = 256; s > 0; s >>= 1) {
        if (tid < s) dred[tid] += dred[tid + s];
        __syncthreads();
    }
    if (tid == 0) g_partial[blockIdx.x] = dred[0];
}

// ---------------- kernel 3: final loss (fp64) ----------------
__global__ void finalize_kernel(float* __restrict__ out, int out_size) {
    __shared__ double s[256];
    int tid = threadIdx.x;
    s[tid] = g_partial[tid] + g_partial[tid + 256];
    __syncthreads();
#pragma unroll
    for (int w = 128; w > 0; w >>= 1) {
        if (tid < w) s[tid] += s[tid + w];
        __syncthreads();
    }
    if (tid == 0 && out_size > LOSS_OFF)
        out[LOSS_OFF] = (float)(1.25 * s[0] / (double)Q_ELEMS);   // (1+BETA)*MSE
}

// ---------------- launch ----------------
extern "C" void kernel_launch(void* const* d_in, const int* in_sizes, int n_in,
                              void* d_out, int out_size) {
    const float* z  = (const float*)d_in[0];
    const float* cb = (const float*)d_in[1];
    float* out = (float*)d_out;

    cudaFuncSetAttribute(vq_main, cudaFuncAttributeMaxDynamicSharedMemorySize, SMEM_TOTAL);

    zsq_kernel<<<MROWS / 256, 256>>>(z);
    split_cb<<<KCODES * 8 / 256, 256>>>(cb);
    vq_main<<<NBLOCKS, NTHREADS, SMEM_TOTAL>>>(z, cb, out, out_size);
    finalize_kernel<<<1, 256>>>(out, out_size);
}

// round 9
// speedup vs baseline: 1.1005x; 1.1005x over previous
#include <cuda_runtime.h>
#include <cstdint>
#include <cfloat>

// ---------------- problem constants ----------------
#define MROWS   65536
#define DDIM    64
#define KCODES  8192
#define TM      128                    // rows per CTA
#define TN      64                     // codes per tile
#define NTILES  128
#define NBLOCKS 512
#define NTHREADS 256
#define Q_ELEMS (MROWS * DDIM)
#define LOSS_OFF Q_ELEMS               // layout: [quantised | loss | indices]
#define IDX_OFF  (Q_ELEMS + 1)
#define FULL_OUT (Q_ELEMS + 1 + MROWS)

// Interleaved split-codebook tile: per code n: 8kk x 4tig x float4
// float4 at [n*132 + kk*16 + tig*4] = (e1[d], e1[d+4], e2[d], e2[d+4]), d = kk*8+tig
// stride 132 floats (528B): g-lanes land on distinct bank quads -> conflict-free LDS.128
#define ES_N_STRIDE   132
#define ES_TILE_FLOATS (64 * ES_N_STRIDE)        // 8448
#define ES_CHUNKS      (ES_TILE_FLOATS / 4)      // 2112 x 16B

#define ZS_STRIDE 68
#define ZS_FLOATS (TM * ZS_STRIDE)               // 8704
// smem: [Zs 8704][zsqS 128][Es0 8448][Es1 8448]
#define ZSQ_OFF   ZS_FLOATS
#define ES0_OFF   (ZS_FLOATS + 128)
#define ES1_OFF   (ES0_OFF + ES_TILE_FLOATS)
#define SMEM_TOTAL ((ES1_OFF + ES_TILE_FLOATS) * 4)   // 102912 B -> 2 CTAs/SM

__device__ double g_partial[NBLOCKS];
__device__ float  g_esplit[NTILES * ES_TILE_FLOATS];   // 4.3 MB

// ---------------- helpers ----------------
__device__ __forceinline__ float tf32rn(float x) {   // RN to tf32 grid
    uint32_t b = __float_as_uint(x);
    uint32_t r = b + 0x00000FFFu + ((b >> 13) & 1u);
    return __uint_as_float(r & 0xFFFFE000u);
}
__device__ __forceinline__ uint32_t smem_u32(const void* p) {
    uint32_t a;
    asm("{ .reg .u64 t; cvta.to.shared.u64 t, %1; cvt.u32.u64 %0, t; }" : "=r"(a) : "l"(p));
    return a;
}
__device__ __forceinline__ void cp16(uint32_t dst, const float* src) {
    asm volatile("cp.async.cg.shared.global [%0], [%1], 16;" :: "r"(dst), "l"(src));
}
#define CP_COMMIT() asm volatile("cp.async.commit_group;" ::: "memory")

// m16n8k8 tf32 mma: D += A*B
__device__ __forceinline__ void mma8(float* d, const uint32_t* a, uint32_t b0, uint32_t b1) {
    asm volatile("mma.sync.aligned.m16n8k8.row.col.f32.tf32.tf32.f32 "
                 "{%0,%1,%2,%3}, {%4,%5,%6,%7}, {%8,%9}, {%0,%1,%2,%3};"
                 : "+f"(d[0]), "+f"(d[1]), "+f"(d[2]), "+f"(d[3])
                 : "r"(a[0]), "r"(a[1]), "r"(a[2]), "r"(a[3]), "r"(b0), "r"(b1));
}

// ---------------- kernel 0: tf32 2-way split of codebook (interleaved) ------
__global__ void split_cb(const float* __restrict__ cb) {
    int idx = blockIdx.x * blockDim.x + threadIdx.x;     // 8192 codes x 8 kk
    if (idx >= KCODES * 8) return;
    int k = idx >> 3, kk = idx & 7;
    int t = k >> 6, n = k & 63;
    const float4* p = (const float4*)(cb + (size_t)k * DDIM + kk * 8);
    float4 x = p[0], y = p[1];
    float e[8] = {x.x, x.y, x.z, x.w, y.x, y.y, y.z, y.w};
    float* base = g_esplit + (size_t)t * ES_TILE_FLOATS + n * ES_N_STRIDE + kk * 16;
#pragma unroll
    for (int tig = 0; tig < 4; tig++) {
        float a = e[tig], b = e[tig + 4];
        float a1 = tf32rn(a), b1 = tf32rn(b);
        *(float4*)(base + tig * 4) = make_float4(a1, b1, a - a1, b - b1);
    }
}

// ---------------- kernel 1: tf32 mma GEMM + quantized argmin ----------------
__global__ void __launch_bounds__(NTHREADS, 2) vq_main(const float* __restrict__ z,
                                                       const float* __restrict__ cb,
                                                       float* __restrict__ out,
                                                       int out_size) {
    extern __shared__ float smem[];
    float* Zs   = smem;                        // [128][68]: raw z, then z2 residuals
    float* zsqS = smem + ZSQ_OFF;
    float* Es0  = smem + ES0_OFF;
    float* Es1  = smem + ES1_OFF;

    const int tid  = threadIdx.x;
    const int lane = tid & 31, wid = tid >> 5;
    const int g    = lane >> 2, tig = lane & 3;
    const int wg   = wid >> 1,  cg  = wid & 1;   // 4 row-groups x 2 code-groups
    const int rowBase = blockIdx.x * TM;
    const int rbase   = wg * 32;
    const int row0s   = (rbase + g) * ZS_STRIDE;
    const int row1s   = (rbase + g + 8) * ZS_STRIDE;

    const bool can_q   = (out_size >= Q_ELEMS);
    const bool can_idx = (out_size >= FULL_OUT);

    const uint32_t es0_u = smem_u32(Es0);
    const uint32_t es1_u = smem_u32(Es1);

    // ---- issue tile-0 codebook copy ----
    {
        const float* src = g_esplit;
#pragma unroll
        for (int i = 0; i < 9; i++) {
            int c = tid + i * NTHREADS;
            if (c < ES_CHUNKS) cp16(es0_u + c * 16, src + c * 4);
        }
        CP_COMMIT();
    }

    // ---- stage raw z tile into Zs ----
#pragma unroll
    for (int i = 0; i < 8; i++) {
        int v = tid + i * NTHREADS;
        int r = v >> 4, c4 = v & 15;
        float4 t4 = ((const float4*)(z + (size_t)(rowBase + r) * DDIM))[c4];
        *(float4*)&Zs[r * ZS_STRIDE + c4 * 4] = t4;
    }
    __syncthreads();

    // ---- inline z_sq (fp64 accumulate per row, correctly-rounded fp32) ----
    if (tid < TM) {
        const float* zr = &Zs[tid * ZS_STRIDE];
        double s = 0.0;
#pragma unroll
        for (int i = 0; i < DDIM; i++) s += (double)zr[i] * (double)zr[i];
        zsqS[tid] = (float)s;
    }

    // ---- build z1 fragments in registers: 2 ratoms x 8 kk x 4 ----
    uint32_t z1f[2][8][4];
#pragma unroll
    for (int r = 0; r < 2; r++) {
#pragma unroll
        for (int kk = 0; kk < 8; kk++) {
            int col = kk * 8 + tig;
            int r0 = row0s + r * 16 * ZS_STRIDE, r1 = row1s + r * 16 * ZS_STRIDE;
            z1f[r][kk][0] = __float_as_uint(tf32rn(Zs[r0 + col]));
            z1f[r][kk][1] = __float_as_uint(tf32rn(Zs[r1 + col]));
            z1f[r][kk][2] = __float_as_uint(tf32rn(Zs[r0 + col + 4]));
            z1f[r][kk][3] = __float_as_uint(tf32rn(Zs[r1 + col + 4]));
        }
    }
    __syncthreads();
    // cg==0 warps overwrite Zs with z2 = z - z1 (each position exactly once)
    if (cg == 0) {
#pragma unroll
        for (int r = 0; r < 2; r++)
#pragma unroll
            for (int kk = 0; kk < 8; kk++) {
                int col = kk * 8 + tig;
                int r0 = row0s + r * 16 * ZS_STRIDE, r1 = row1s + r * 16 * ZS_STRIDE;
                Zs[r0 + col]     -= __uint_as_float(z1f[r][kk][0]);
                Zs[r1 + col]     -= __uint_as_float(z1f[r][kk][1]);
                Zs[r0 + col + 4] -= __uint_as_float(z1f[r][kk][2]);
                Zs[r1 + col + 4] -= __uint_as_float(z1f[r][kk][3]);
            }
    }
    __syncthreads();

    float zsqv[2][2];
#pragma unroll
    for (int r = 0; r < 2; r++) {
        zsqv[r][0] = zsqS[rbase + r * 16 + g];
        zsqv[r][1] = zsqS[rbase + r * 16 + g + 8];
    }

    float best[2][2];
    int   bidx[2][2];
#pragma unroll
    for (int r = 0; r < 2; r++)
#pragma unroll
        for (int h = 0; h < 2; h++) { best[r][h] = FLT_MAX; bidx[r][h] = 0; }

    // ---------------- mainloop over 128 code tiles ----------------
    for (int t = 0; t < NTILES; t++) {
        if (t + 1 < NTILES) {
            const float* src = g_esplit + (size_t)(t + 1) * ES_TILE_FLOATS;
            uint32_t du = ((t + 1) & 1) ? es1_u : es0_u;
#pragma unroll
            for (int i = 0; i < 9; i++) {
                int c = tid + i * NTHREADS;
                if (c < ES_CHUNKS) cp16(du + c * 16, src + c * 4);
            }
            CP_COMMIT();
            asm volatile("cp.async.wait_group 1;" ::: "memory");
        } else {
            asm volatile("cp.async.wait_group 0;" ::: "memory");
        }
        __syncthreads();

        const float* E = (t & 1) ? Es1 : Es0;

        float acc[2][4][4];
#pragma unroll
        for (int r = 0; r < 2; r++)
#pragma unroll
            for (int na = 0; na < 4; na++)
#pragma unroll
                for (int c = 0; c < 4; c++) acc[r][na][c] = 0.0f;

#pragma unroll
        for (int kk = 0; kk < 8; kk++) {
            int col = kk * 8 + tig;
            uint32_t z2a[4], z2b[4];
            z2a[0] = __float_as_uint(Zs[row0s + col]);
            z2a[1] = __float_as_uint(Zs[row1s + col]);
            z2a[2] = __float_as_uint(Zs[row0s + col + 4]);
            z2a[3] = __float_as_uint(Zs[row1s + col + 4]);
            z2b[0] = __float_as_uint(Zs[row0s + 16 * ZS_STRIDE + col]);
            z2b[1] = __float_as_uint(Zs[row1s + 16 * ZS_STRIDE + col]);
            z2b[2] = __float_as_uint(Zs[row0s + 16 * ZS_STRIDE + col + 4]);
            z2b[3] = __float_as_uint(Zs[row1s + 16 * ZS_STRIDE + col + 4]);
#pragma unroll
            for (int na = 0; na < 4; na++) {
                int n = cg * 32 + na * 8 + g;
                const float4 b4 = *(const float4*)(E + n * ES_N_STRIDE + kk * 16 + tig * 4);
                uint32_t b1x = __float_as_uint(b4.x), b1y = __float_as_uint(b4.y);
                uint32_t b2x = __float_as_uint(b4.z), b2y = __float_as_uint(b4.w);
                // small terms first, dominant last
                mma8(acc[0][na], z1f[0][kk], b2x, b2y);   // z1*e2
                mma8(acc[1][na], z1f[1][kk], b2x, b2y);
                mma8(acc[0][na], z2a,        b1x, b1y);   // z2*e1
                mma8(acc[1][na], z2b,        b1x, b1y);
                mma8(acc[0][na], z1f[0][kk], b1x, b1y);   // z1*e1
                mma8(acc[1][na], z1f[1][kk], b1x, b1y);
            }
        }

        // quantized scores: s = RN(z_sq - 2*dot); running argmin, ascending idx
#pragma unroll
        for (int r = 0; r < 2; r++) {
#pragma unroll
            for (int na = 0; na < 4; na++) {
                int code0 = t * TN + cg * 32 + na * 8 + 2 * tig;
                float s0 = fmaf(-2.0f, acc[r][na][0], zsqv[r][0]);
                float s1 = fmaf(-2.0f, acc[r][na][1], zsqv[r][0]);
                float s2 = fmaf(-2.0f, acc[r][na][2], zsqv[r][1]);
                float s3 = fmaf(-2.0f, acc[r][na][3], zsqv[r][1]);
                if (s0 < best[r][0]) { best[r][0] = s0; bidx[r][0] = code0; }
                if (s1 < best[r][0]) { best[r][0] = s1; bidx[r][0] = code0 + 1; }
                if (s2 < best[r][1]) { best[r][1] = s2; bidx[r][1] = code0; }
                if (s3 < best[r][1]) { best[r][1] = s3; bidx[r][1] = code0 + 1; }
            }
        }
        __syncthreads();
    }

    // ---- reduce across tig lanes (same rows), lowest-index tie-break ----
#pragma unroll
    for (int r = 0; r < 2; r++) {
#pragma unroll
        for (int h = 0; h < 2; h++) {
            float bv = best[r][h];
            int   bi = bidx[r][h];
#pragma unroll
            for (int off = 1; off <= 2; off <<= 1) {
                float ov = __shfl_xor_sync(0xFFFFFFFFu, bv, off);
                int   oi = __shfl_xor_sync(0xFFFFFFFFu, bi, off);
                if (ov < bv || (ov == bv && oi < bi)) { bv = ov; bi = oi; }
            }
            best[r][h] = bv; bidx[r][h] = bi;
        }
    }

    float2* red = (float2*)Zs;    // [128][2] candidates from the 2 code-groups
    if (tig == 0) {
#pragma unroll
        for (int r = 0; r < 2; r++)
#pragma unroll
            for (int h = 0; h < 2; h++)
                red[(rbase + r * 16 + g + h * 8) * 2 + cg] =
                    make_float2(best[r][h], __int_as_float(bidx[r][h]));
    }
    __syncthreads();

    // ---- final per-row pick + outputs (exact quantised_st) + fp64 loss ----
    double lsum = 0.0;
    if (tid < TM) {
        int row = rowBase + tid;
        float2 c0 = red[tid * 2 + 0];
        float2 c1 = red[tid * 2 + 1];
        float bv = c0.x; int bi = __float_as_int(c0.y);
        int i1 = __float_as_int(c1.y);
        if (c1.x < bv || (c1.x == bv && i1 < bi)) { bv = c1.x; bi = i1; }
        if (can_idx) out[IDX_OFF + row] = (float)bi;
        const float4* q4 = (const float4*)(cb + (size_t)bi * DDIM);
        const float4* z4 = (const float4*)(z + (size_t)row * DDIM);
        float4* o4 = (float4*)(out + (size_t)row * DDIM);
#pragma unroll
        for (int i = 0; i < DDIM / 4; i++) {
            float4 q = q4[i];
            float4 zz = z4[i];
            float dx = q.x - zz.x, dy = q.y - zz.y, dz = q.z - zz.z, dw = q.w - zz.w;
            if (can_q) {
                float4 o;
                o.x = zz.x + dx; o.y = zz.y + dy; o.z = zz.z + dz; o.w = zz.w + dw;
                o4[i] = o;
            }
            lsum += (double)(dx * dx) + (double)(dy * dy)
                  + (double)(dz * dz) + (double)(dw * dw);
        }
    }
    double* dred = (double*)(Zs + 1024);     // byte 4096.., clear of red[0..255]
    __syncthreads();
    dred[tid] = lsum;
    __syncthreads();
#pragma unroll
    for (int s = 128; s > 0; s >>= 1) {
        if (tid < s) dred[tid] += dred[tid + s];
        __syncthreads();
    }
    if (tid == 0) g_partial[blockIdx.x] = dred[0];
}

// ---------------- kernel 2: final loss (fp64) ----------------
__global__ void finalize_kernel(float* __restrict__ out, int out_size) {
    __shared__ double s[256];
    int tid = threadIdx.x;
    s[tid] = g_partial[tid] + g_partial[tid + 256];
    __syncthreads();
#pragma unroll
    for (int w = 128; w > 0; w >>= 1) {
        if (tid < w) s[tid] += s[tid + w];
        __syncthreads();
    }
    if (tid == 0 && out_size > LOSS_OFF)
        out[LOSS_OFF] = (float)(1.25 * s[0] / (double)Q_ELEMS);   // (1+BETA)*MSE
}

// ---------------- launch ----------------
extern "C" void kernel_launch(void* const* d_in, const int* in_sizes, int n_in,
                              void* d_out, int out_size) {
    const float* z  = (const float*)d_in[0];
    const float* cb = (const float*)d_in[1];
    float* out = (float*)d_out;

    cudaFuncSetAttribute(vq_main, cudaFuncAttributeMaxDynamicSharedMemorySize, SMEM_TOTAL);

    split_cb<<<KCODES * 8 / 256, 256>>>(cb);
    vq_main<<<NBLOCKS, NTHREADS, SMEM_TOTAL>>>(z, cb, out, out_size);
    finalize_kernel<<<1, 256>>>(out, out_size);
}

// round 11
// speedup vs baseline: 1.1359x; 1.0322x over previous
#include <cuda_runtime.h>
#include <cuda_fp16.h>
#include <cstdint>
#include <cfloat>
#include <climits>

// ---------------- problem constants ----------------
#define MROWS   65536
#define DDIM    64
#define KCODES  8192
#define TM      128
#define TN      64
#define NTILES  128
#define NBLOCKS 512
#define NTHREADS 256
#define Q_ELEMS (MROWS * DDIM)
#define LOSS_OFF Q_ELEMS
#define IDX_OFF  (Q_ELEMS + 1)
#define FULL_OUT (Q_ELEMS + 1 + MROWS)

#define ESCALE  16384.0f     // exact 2^14: e*2^14 in [-2,2], normal fp16 range
#define WS      0.2f         // certification window, SCALED dot units (=1.22e-5 raw, ~52 sigma)
#define SENT    INT_MAX

// fp16 codebook tile image: 64 codes x 80 halves (64 used + pad)
// per (n, ks, tig): halves e[k],e[k+1],e[k+8],e[k+9], k = ks*16 + tig*2  (scaled)
#define EH_N_STRIDE    80
#define EH_TILE_HALVES (64 * EH_N_STRIDE)     // 5120
#define EH_TILE_BYTES  (EH_TILE_HALVES * 2)   // 10240
#define EH_CHUNKS      (EH_TILE_BYTES / 16)   // 640

#define ZS_STRIDE 68
// smem byte offsets
#define ZSQ_B   34816
#define ES0_B   35328
#define ES1_B   (ES0_B + EH_TILE_BYTES)       // 45568
#define M_B     (ES1_B + EH_TILE_BYTES)       // 55808: merge 128 rows x 8 lists x 32B
#define CH_B    (M_B + 32768)                 // 88576: chosen idx 512
#define FL_B    (CH_B + 512)                  // flags 512
#define RED_B   (FL_B + 512)                  // 2048
#define DRED_B  (RED_B + 2048)                // 2048
#define SMEM_TOTAL (DRED_B + 2048)            // 93696 -> 2 CTAs/SM

__device__ double   g_partial[NBLOCKS];
__device__ uint16_t g_efp16[NTILES * EH_TILE_HALVES];   // 1.3 MB scaled fp16 tiles

// ---------------- helpers ----------------
__device__ __forceinline__ uint32_t smem_u32(const void* p) {
    uint32_t a;
    asm("{ .reg .u64 t; cvta.to.shared.u64 t, %1; cvt.u32.u64 %0, t; }" : "=r"(a) : "l"(p));
    return a;
}
__device__ __forceinline__ void cp16(uint32_t dst, const void* src) {
    asm volatile("cp.async.cg.shared.global [%0], [%1], 16;" :: "r"(dst), "l"(src));
}
#define CP_COMMIT() asm volatile("cp.async.commit_group;" ::: "memory")

__device__ __forceinline__ uint32_t pkhf(float lo, float hi) {
    __half2 h = __floats2half2_rn(lo, hi);
    return *(uint32_t*)&h;
}
// m16n8k16 fp16 mma, fp32 accum: D += A*B
__device__ __forceinline__ void mma16(float* d, const uint32_t* a, uint32_t b0, uint32_t b1) {
    asm volatile("mma.sync.aligned.m16n8k16.row.col.f32.f16.f16.f32 "
                 "{%0,%1,%2,%3}, {%4,%5,%6,%7}, {%8,%9}, {%0,%1,%2,%3};"
                 : "+f"(d[0]), "+f"(d[1]), "+f"(d[2]), "+f"(d[3])
                 : "r"(a[0]), "r"(a[1]), "r"(a[2]), "r"(a[3]), "r"(b0), "r"(b1));
}

// ---------------- kernel 0: codebook -> scaled fp16 fragment tiles ---------
__global__ void prep_cb(const float* __restrict__ cb) {
    int k = blockIdx.x * blockDim.x + threadIdx.x;
    if (k >= KCODES) return;
    int t = k >> 6, n = k & 63;
    float v[64];
    const float4* p = (const float4*)(cb + (size_t)k * DDIM);
#pragma unroll
    for (int i = 0; i < 16; i++) {
        float4 x = p[i];
        v[4 * i] = x.x; v[4 * i + 1] = x.y; v[4 * i + 2] = x.z; v[4 * i + 3] = x.w;
    }
    uint16_t* base = g_efp16 + (size_t)t * EH_TILE_HALVES + n * EH_N_STRIDE;
#pragma unroll
    for (int ks = 0; ks < 4; ks++) {
#pragma unroll
        for (int tg = 0; tg < 4; tg++) {
            int kd = ks * 16 + tg * 2;
            ushort4 u;
            u.x = __half_as_ushort(__float2half_rn(v[kd]     * ESCALE));
            u.y = __half_as_ushort(__float2half_rn(v[kd + 1] * ESCALE));
            u.z = __half_as_ushort(__float2half_rn(v[kd + 8] * ESCALE));
            u.w = __half_as_ushort(__float2half_rn(v[kd + 9] * ESCALE));
            *(ushort4*)(base + ks * 16 + tg * 4) = u;
        }
    }
}

// ---------------- kernel 1: fp16 approx GEMM + certify + exact refine ------
__global__ void __launch_bounds__(NTHREADS, 2) vq_main(const float* __restrict__ z,
                                                       const float* __restrict__ cb,
                                                       float* __restrict__ out,
                                                       int out_size) {
    extern __shared__ char smem[];
    float*  Zs     = (float*)smem;                 // [128][68] raw fp32 z
    float*  zsqS   = (float*)(smem + ZSQ_B);
    float*  Mred   = (float*)(smem + M_B);         // [128][8][8 words]
    int*    chosen = (int*)(smem + CH_B);
    int*    flagFS = (int*)(smem + FL_B);
    float2* red2   = (float2*)(smem + RED_B);
    double* dred   = (double*)(smem + DRED_B);

    const int tid  = threadIdx.x;
    const int lane = tid & 31, wid = tid >> 5;
    const int g    = lane >> 2, tig = lane & 3;
    const int wg   = wid >> 1,  cg  = wid & 1;
    const int rowBase = blockIdx.x * TM;
    const int rbase   = wg * 32;

    const bool can_q   = (out_size >= Q_ELEMS);
    const bool can_idx = (out_size >= FULL_OUT);

    const uint32_t es0_u = smem_u32(smem + ES0_B);
    const uint32_t es1_u = smem_u32(smem + ES1_B);

    // ---- issue tile-0 codebook copy ----
    {
        const char* src = (const char*)g_efp16;
#pragma unroll
        for (int i = 0; i < 3; i++) {
            int c = tid + i * NTHREADS;
            if (c < EH_CHUNKS) cp16(es0_u + c * 16, src + c * 16);
        }
        CP_COMMIT();
    }

    // ---- stage raw z tile ----
#pragma unroll
    for (int i = 0; i < 8; i++) {
        int v = tid + i * NTHREADS;
        int r = v >> 4, c4 = v & 15;
        float4 t4 = ((const float4*)(z + (size_t)(rowBase + r) * DDIM))[c4];
        *(float4*)&Zs[r * ZS_STRIDE + c4 * 4] = t4;
    }
    if (tid < 128) flagFS[tid] = 0;
    __syncthreads();

    // ---- z_sq: fp64 accumulate -> correctly rounded fp32 ----
    if (tid < TM) {
        const float* zr = &Zs[tid * ZS_STRIDE];
        double s = 0.0;
#pragma unroll
        for (int i = 0; i < DDIM; i++) s += (double)zr[i] * (double)zr[i];
        zsqS[tid] = (float)s;
    }

    // ---- fp16 A fragments: 2 ratoms x 4 ksteps x 4 regs ----
    uint32_t af[2][4][4];
#pragma unroll
    for (int r = 0; r < 2; r++) {
        int m0 = (rbase + r * 16 + g) * ZS_STRIDE;
        int m1 = m0 + 8 * ZS_STRIDE;
#pragma unroll
        for (int ks = 0; ks < 4; ks++) {
            int kd = ks * 16 + tig * 2;
            af[r][ks][0] = pkhf(Zs[m0 + kd],     Zs[m0 + kd + 1]);
            af[r][ks][1] = pkhf(Zs[m1 + kd],     Zs[m1 + kd + 1]);
            af[r][ks][2] = pkhf(Zs[m0 + kd + 8], Zs[m0 + kd + 9]);
            af[r][ks][3] = pkhf(Zs[m1 + kd + 8], Zs[m1 + kd + 9]);
        }
    }
    __syncthreads();

    // top-4 approx (scaled) dots per row-slot; indices for top-3
    float b1[4], b2[4], b3[4], b4[4];
    int   i1[4], i2[4], i3[4];
#pragma unroll
    for (int s = 0; s < 4; s++) {
        b1[s] = -FLT_MAX; b2[s] = -FLT_MAX; b3[s] = -FLT_MAX; b4[s] = -FLT_MAX;
        i1[s] = SENT; i2[s] = SENT; i3[s] = SENT;
    }

    // ---------------- mainloop: 128 tiles of 64 codes ----------------
    for (int t = 0; t < NTILES; t++) {
        if (t + 1 < NTILES) {
            const char* src = (const char*)(g_efp16 + (size_t)(t + 1) * EH_TILE_HALVES);
            uint32_t du = ((t + 1) & 1) ? es1_u : es0_u;
#pragma unroll
            for (int i = 0; i < 3; i++) {
                int c = tid + i * NTHREADS;
                if (c < EH_CHUNKS) cp16(du + c * 16, src + c * 16);
            }
            CP_COMMIT();
            asm volatile("cp.async.wait_group 1;" ::: "memory");
        } else {
            asm volatile("cp.async.wait_group 0;" ::: "memory");
        }
        __syncthreads();

        const char* E = smem + ((t & 1) ? ES1_B : ES0_B);

        float acc[2][4][4];
#pragma unroll
        for (int r = 0; r < 2; r++)
#pragma unroll
            for (int na = 0; na < 4; na++)
#pragma unroll
                for (int c = 0; c < 4; c++) acc[r][na][c] = 0.0f;

#pragma unroll
        for (int ks = 0; ks < 4; ks++) {
#pragma unroll
            for (int na = 0; na < 4; na++) {
                int n = cg * 32 + na * 8 + g;
                uint2 b = *(const uint2*)(E + (n * EH_N_STRIDE + ks * 16 + tig * 4) * 2);
                mma16(acc[0][na], af[0][ks], b.x, b.y);
                mma16(acc[1][na], af[1][ks], b.x, b.y);
            }
        }

        // top-4 insert; common path = single compare
#pragma unroll
        for (int r = 0; r < 2; r++) {
#pragma unroll
            for (int na = 0; na < 4; na++) {
#pragma unroll
                for (int c = 0; c < 4; c++) {
                    float v = acc[r][na][c];
                    int   s = r * 2 + (c >> 1);
                    if (v > b4[s]) {
                        int id = t * TN + cg * 32 + na * 8 + 2 * tig + (c & 1);
                        if (v > b2[s]) {
                            if (v > b1[s]) {
                                b4[s] = b3[s]; b3[s] = b2[s]; i3[s] = i2[s];
                                b2[s] = b1[s]; i2[s] = i1[s];
                                b1[s] = v; i1[s] = id;
                            } else {
                                b4[s] = b3[s]; b3[s] = b2[s]; i3[s] = i2[s];
                                b2[s] = v; i2[s] = id;
                            }
                        } else if (v > b3[s]) {
                            b4[s] = b3[s]; b3[s] = v; i3[s] = id;
                        } else b4[s] = v;
                    }
                }
            }
        }
        __syncthreads();
    }

    // ---- dump per-lane lists to smem: [row][list = cg*4+tig] ----
#pragma unroll
    for (int s = 0; s < 4; s++) {
        int row = rbase + (s >> 1) * 16 + g + (s & 1) * 8;
        float* m = &Mred[(row * 8 + cg * 4 + tig) * 8];
        m[0] = b1[s]; m[1] = b2[s]; m[2] = b3[s]; m[3] = b4[s];
        m[4] = __int_as_float(i1[s]); m[5] = __int_as_float(i2[s]);
        m[6] = __int_as_float(i3[s]);
    }
    __syncthreads();

    // ---- thread-per-row merge of 8 lists + decision ----
    if (tid < TM) {
        float t1 = -FLT_MAX, t2 = -FLT_MAX, t3 = -FLT_MAX, t4 = -FLT_MAX;
        int   j1 = SENT, j2 = SENT, j3 = SENT;
#pragma unroll
        for (int l = 0; l < 8; l++) {
            const float* m = &Mred[(tid * 8 + l) * 8];
#pragma unroll
            for (int e = 0; e < 4; e++) {
                float v = m[e];
                if (v <= t4) break;
                int id = (e < 3) ? __float_as_int(m[4 + e]) : SENT;
                if (v > t2) {
                    if (v > t1) { t4 = t3; t3 = t2; j3 = j2; t2 = t1; j2 = j1; t1 = v; j1 = id; }
                    else        { t4 = t3; t3 = t2; j3 = j2; t2 = v; j2 = id; }
                } else if (v > t3) { t4 = t3; t3 = v; j3 = id; }
                else t4 = v;
            }
        }

        float thr = t1 - WS;
        if (t2 < thr && j1 != SENT) {
            chosen[tid] = j1;                       // certified winner (strict, no tie)
        } else {
            int  cand[3]; int nc = 0; bool ok = true;
            if (t3 < thr) {                          // winner in {j1,j2}
                cand[0] = j1; cand[1] = j2; nc = 2;
                ok = (j1 != SENT) && (j2 != SENT);
            } else if (t4 < thr) {                   // winner in {j1,j2,j3}
                cand[0] = j1; cand[1] = j2; cand[2] = j3; nc = 3;
                ok = (j1 != SENT) && (j2 != SENT) && (j3 != SENT);
            } else ok = false;
            if (!ok) {
                flagFS[tid] = 1;
            } else {
                // exact fp32 rescore, bucketed compare, lowest-index ties
                float zq = zsqS[tid];
                const float* zr = &Zs[tid * ZS_STRIDE];
                float bs = FLT_MAX; int bi = SENT;
                for (int q = 0; q < nc; q++) {
                    int j = cand[q];
                    const float* cp = cb + (size_t)j * DDIM;
                    float dot = 0.f;
#pragma unroll
                    for (int d = 0; d < DDIM; d++) dot = fmaf(cp[d], zr[d], dot);
                    float s = fmaf(-2.0f, dot, zq);
                    if (s < bs || (s == bs && j < bi)) { bs = s; bi = j; }
                }
                chosen[tid] = bi;
            }
        }
    }
    __syncthreads();

    // ---- exact full-row rescan for flagged rows (CTA-cooperative) ----
    for (int r = 0; r < TM; r++) {
        if (flagFS[r]) {
            float zq = zsqS[r];
            const float* zr = &Zs[r * ZS_STRIDE];
            float bs = FLT_MAX; int bi = SENT;
            for (int jj = 0; jj < KCODES / NTHREADS; jj++) {
                int j = tid + jj * NTHREADS;
                const float* cp = cb + (size_t)j * DDIM;
                float dot = 0.f;
#pragma unroll
                for (int d = 0; d < DDIM; d++) dot = fmaf(cp[d], zr[d], dot);
                float s = fmaf(-2.0f, dot, zq);
                if (s < bs || (s == bs && j < bi)) { bs = s; bi = j; }
            }
            red2[tid] = make_float2(bs, __int_as_float(bi));
            __syncthreads();
#pragma unroll
            for (int s2 = NTHREADS / 2; s2 > 0; s2 >>= 1) {
                if (tid < s2) {
                    float2 a = red2[tid], o = red2[tid + s2];
                    int ai = __float_as_int(a.y), oi = __float_as_int(o.y);
                    if (o.x < a.x || (o.x == a.x && oi < ai)) red2[tid] = o;
                }
                __syncthreads();
            }
            if (tid == 0) chosen[r] = __float_as_int(red2[0].y);
            __syncthreads();
        }
    }

    // ---- emit: indices, exact quantised_st (= z + (q - z)), fp64 loss ----
    double lsum = 0.0;
    if (tid < TM) {
        int row = rowBase + tid;
        int bi = chosen[tid];
        if (can_idx) out[IDX_OFF + row] = (float)bi;
        const float4* q4 = (const float4*)(cb + (size_t)bi * DDIM);
        const float* zr = &Zs[tid * ZS_STRIDE];
        float4* o4 = (float4*)(out + (size_t)row * DDIM);
#pragma unroll
        for (int i = 0; i < DDIM / 4; i++) {
            float4 q = q4[i];
            float zx = zr[4 * i], zy = zr[4 * i + 1], zz2 = zr[4 * i + 2], zw = zr[4 * i + 3];
            float dx = q.x - zx, dy = q.y - zy, dz = q.z - zz2, dw = q.w - zw;
            if (can_q) {
                float4 o;
                o.x = zx + dx; o.y = zy + dy; o.z = zz2 + dz; o.w = zw + dw;
                o4[i] = o;
            }
            lsum += (double)(dx * dx) + (double)(dy * dy)
                  + (double)(dz * dz) + (double)(dw * dw);
        }
    }
    dred[tid] = lsum;
    __syncthreads();
#pragma unroll
    for (int s = 128; s > 0; s >>= 1) {
        if (tid < s) dred[tid] += dred[tid + s];
        __syncthreads();
    }
    if (tid == 0) g_partial[blockIdx.x] = dred[0];
}

// ---------------- kernel 2: final loss (fp64) ----------------
__global__ void finalize_kernel(float* __restrict__ out, int out_size) {
    __shared__ double s[256];
    int tid = threadIdx.x;
    s[tid] = g_partial[tid] + g_partial[tid + 256];
    __syncthreads();
#pragma unroll
    for (int w = 128; w > 0; w >>= 1) {
        if (tid < w) s[tid] += s[tid + w];
        __syncthreads();
    }
    if (tid == 0 && out_size > LOSS_OFF)
        out[LOSS_OFF] = (float)(1.25 * s[0] / (double)Q_ELEMS);   // (1+BETA)*MSE
}

// ---------------- launch ----------------
extern "C" void kernel_launch(void* const* d_in, const int* in_sizes, int n_in,
                              void* d_out, int out_size) {
    const float* z  = (const float*)d_in[0];
    const float* cb = (const float*)d_in[1];
    float* out = (float*)d_out;

    cudaFuncSetAttribute(vq_main, cudaFuncAttributeMaxDynamicSharedMemorySize, SMEM_TOTAL);

    prep_cb<<<KCODES / 256, 256>>>(cb);
    vq_main<<<NBLOCKS, NTHREADS, SMEM_TOTAL>>>(z, cb, out, out_size);
    finalize_kernel<<<1, 256>>>(out, out_size);
}